// round 9
// baseline (speedup 1.0000x reference)
#include <cuda_runtime.h>
#include <cstdint>

#define BB 32
#define NN 4096
#define DD 768
#define KK 1024
#define CHUNK 512
#define NCHUNK 8
#define ROWS_PER_BLK 8

typedef unsigned long long u64;

__device__ int g_topk[BB * KK];
__device__ u64 g_scratch[BB * NN];        // per-batch: 8 sorted descending chunks
__device__ volatile int g_arrive[BB];      // per-batch CTA arrival counters (reset by gather)

// Map float to uint with ascending unsigned order == ascending float order.
__device__ __forceinline__ unsigned f2ord(float f) {
    unsigned u = __float_as_uint(f);
    return (u & 0x80000000u) ? ~u : (u | 0x80000000u);
}

// ---------------------------------------------------------------------------
// Fused sort + rank-merge. CTA (b,c), 512 threads, 1 key/thread.
// Phase 1: bitonic-sort chunk c of batch b descending by composite key
//          (ord << 12) | (4095 - idx)  => jax.lax.top_k order. 45 stages:
//          j<=16 shfl_xor, j>=32 smem. Write sorted chunk to g_scratch.
// Phase 2: arrive on g_arrive[b]; spin until all 8 chunks of batch b are
//          published (all 256 CTAs are co-resident: launch_bounds(512,2)
//          guarantees capacity >= 296 CTAs). Then load the 7 sibling chunks
//          into smem and compute rank = t + sum count(key' > key) via 7
//          interleaved 9-step binary searches. Write idx iff rank < 1024.
// ---------------------------------------------------------------------------
__global__ __launch_bounds__(512, 2) void sort_merge_kernel(const float* __restrict__ sig) {
    __shared__ u64 sm[(NCHUNK - 1) * CHUNK];   // 28 KB; sort uses sm[0..511]
    const int b = blockIdx.x >> 3;
    const int c = blockIdx.x & 7;
    const int t = threadIdx.x;

    // ---- Phase 1: sort ----
    const int g = c * CHUNK + t;
    float v = sig[(size_t)b * NN + g];
    u64 r = ((u64)f2ord(v) << 12) | (u64)(4095 - g);

    #pragma unroll
    for (int k = 2; k <= CHUNK; k <<= 1) {
        #pragma unroll
        for (int j = k >> 1; j > 0; j >>= 1) {
            bool keep_max = (((t & k) == 0) == ((t & j) == 0));
            u64 o;
            if (j >= 32) {
                __syncthreads();
                sm[t] = r;
                __syncthreads();
                o = sm[t ^ j];
            } else {
                o = __shfl_xor_sync(0xffffffffu, r, j);
            }
            r = keep_max ? (r > o ? r : o) : (r < o ? r : o);
        }
    }

    g_scratch[(size_t)b * NN + g] = r;

    // ---- publish + device-wide per-batch barrier ----
    __threadfence();            // order scratch stores before the arrival
    __syncthreads();            // all threads' stores+fences done
    if (t == 0) {
        atomicAdd((int*)&g_arrive[b], 1);
        while (g_arrive[b] < NCHUNK) { }   // volatile read (L2), spin
    }
    __syncthreads();
    __threadfence();            // acquire: order spin-observation before loads

    // ---- Phase 2: rank merge ----
    const u64* base = g_scratch + (size_t)b * NN;
    #pragma unroll
    for (int o = 0; o < NCHUNK - 1; o++) {
        int oc = o + (o >= c ? 1 : 0);
        sm[o * CHUNK + t] = base[oc * CHUNK + t];
    }
    __syncthreads();

    int cnt[NCHUNK - 1];
    #pragma unroll
    for (int o = 0; o < NCHUNK - 1; o++) cnt[o] = 0;

    #pragma unroll
    for (int s = CHUNK / 2; s >= 1; s >>= 1) {
        #pragma unroll
        for (int o = 0; o < NCHUNK - 1; o++) {
            if (sm[o * CHUNK + cnt[o] + s - 1] > r) cnt[o] += s;
        }
    }

    int rank = t;
    #pragma unroll
    for (int o = 0; o < NCHUNK - 1; o++) rank += cnt[o];

    if (rank < KK)
        g_topk[b * KK + rank] = 4095 - (int)(r & 0xFFFu);
}

// ---------------------------------------------------------------------------
// Gather (unchanged, ~27.8us wall = ~7.2TB/s effective): 8 rows/CTA, 192 thr.
// Also resets the arrival counters for the next graph replay (stream-ordered
// after all spins of the current replay have completed).
// ---------------------------------------------------------------------------
__global__ __launch_bounds__(192) void gather_kernel(const float4* __restrict__ x,
                                                     float4* __restrict__ out) {
    if (blockIdx.x == 0 && threadIdx.x < BB)
        g_arrive[threadIdx.x] = 0;

    const int base = blockIdx.x * ROWS_PER_BLK;
    const int tid  = threadIdx.x;

    const float4* srcs[ROWS_PER_BLK];
    #pragma unroll
    for (int r = 0; r < ROWS_PER_BLK; r++) {
        int row = base + r;
        int b   = row / (KK + 1);
        int rr  = row - b * (KK + 1);
        int src_row = (rr == 0) ? 0 : (1 + g_topk[b * KK + rr - 1]);
        srcs[r] = x + ((size_t)b * (NN + 1) + (size_t)src_row) * (DD / 4);
    }

    float4 vals[ROWS_PER_BLK];
    #pragma unroll
    for (int r = 0; r < ROWS_PER_BLK; r++)
        vals[r] = __ldcs(srcs[r] + tid);

    #pragma unroll
    for (int r = 0; r < ROWS_PER_BLK; r++)
        out[(size_t)(base + r) * (DD / 4) + tid] = vals[r];
}

extern "C" void kernel_launch(void* const* d_in, const int* in_sizes, int n_in,
                              void* d_out, int out_size) {
    const float* x   = (const float*)d_in[0];   // [B, N+1, D] fp32
    const float* sig = (const float*)d_in[1];   // [B, N] fp32
    (void)in_sizes; (void)n_in; (void)out_size;

    sort_merge_kernel<<<BB * NCHUNK, CHUNK>>>(sig);
    gather_kernel<<<BB * (KK + 1) / ROWS_PER_BLK, 192>>>((const float4*)x, (float4*)d_out);
}